// round 7
// baseline (speedup 1.0000x reference)
#include <cuda_runtime.h>
#include <cuda_bf16.h>
#include <cstdint>

#define T_SEQ 128
#define NBATCH 2048
#define HDIM  128
#define GDIM  384
#define XDIM  38
#define TB    16

// ---------------- device scratch ----------------
__device__ float   g_gi[(size_t)T_SEQ * NBATCH * GDIM];
__device__ float   g_hall[(size_t)NBATCH * T_SEQ * HDIM];  // [b][t][j]
__device__ float   g_h0[(size_t)NBATCH * HDIM];
__device__ float   g_h1[(size_t)NBATCH * HDIM];
__device__ float4  g_dWhh4[32 * GDIM];
__device__ float   g_Wrz_rm[256 * HDIM];
__device__ float   g_Wcn_rm[128 * HDIM];
__device__ float   g_bcomb[GDIM];
__device__ float   g_brz[256];
// int8 2-level split weights (+ per-row scale premultiplied by 1/126)
__device__ int8_t  g_eW8hi[GDIM * HDIM];
__device__ int8_t  g_eW8lo[GDIM * HDIM];
__device__ int8_t  g_dW8hi[512 * HDIM];
__device__ int8_t  g_dW8lo[512 * HDIM];
__device__ float   g_ealpha[GDIM];
__device__ float   g_dalpha[512];

__device__ __forceinline__ float sigf(float x)  { return __fdividef(1.f, 1.f + __expf(-x)); }
__device__ __forceinline__ float tanhf_(float x){ return __fdividef(2.f, 1.f + __expf(-2.f * x)) - 1.f; }

__device__ __forceinline__ uint32_t smem_u32(const void* p) {
    uint32_t a;
    asm("{ .reg .u64 t; cvta.to.shared.u64 t, %1; cvt.u32.u64 %0, t; }" : "=r"(a) : "l"(p));
    return a;
}

#define LDSM4(r, a) \
    asm volatile("ldmatrix.sync.aligned.m8n8.x4.shared.b16 {%0,%1,%2,%3}, [%4];" \
        : "=r"((r)[0]), "=r"((r)[1]), "=r"((r)[2]), "=r"((r)[3]) : "r"(a))

#define IMMA16832(d, a, b0, b1) \
    asm volatile("mma.sync.aligned.m16n8k32.row.col.s32.s8.s8.s32 " \
        "{%0,%1,%2,%3}, {%4,%5,%6,%7}, {%8,%9}, {%0,%1,%2,%3};" \
        : "+r"((d)[0]), "+r"((d)[1]), "+r"((d)[2]), "+r"((d)[3]) \
        : "r"((a)[0]), "r"((a)[1]), "r"((a)[2]), "r"((a)[3]), "r"(b0), "r"(b1))

#define WSTR 144          // int8 row stride in smem (16B aligned, conflict-free ldmatrix)
#define GSTR 17           // G float stride

// dec smem map
#define D_WHI 0
#define D_WLO 73728       // + 512*144
#define D_G   147456      // + 512*144
#define D_H   182272      // + 512*17*4
#define D_BHI 190464      // + 2048*4
#define D_BLO 192768      // + 16*144
#define D_SZ  195072
// enc smem map
#define E_WHI 0
#define E_WLO 55296       // + 384*144
#define E_G   110592      // + 384*144
#define E_H   136704      // + 384*17*4
#define E_BHI 144896      // + 2048*4
#define E_BLO 147200
#define E_SZ  149504

// ---------------- weight prep (fp32 composition) ----------------
__global__ void prep_kernel(const float* __restrict__ dWhh,
                            const float* __restrict__ dWih, const float* __restrict__ linW,
                            const float* __restrict__ linb, const float* __restrict__ dbih,
                            const float* __restrict__ dbhh)
{
    int g = blockIdx.x * 128 + threadIdx.x;
    if (g >= GDIM) return;

    for (int kc = 0; kc < 32; ++kc) {
        const float* d = dWhh + g * HDIM + kc * 4;
        g_dWhh4[kc * GDIM + g] = make_float4(d[0], d[1], d[2], d[3]);
    }

    float wih[XDIM];
#pragma unroll
    for (int p = 0; p < XDIM; ++p) wih[p] = dWih[g * XDIM + p];

    float bc = dbih[g];
#pragma unroll
    for (int p = 0; p < XDIM; ++p) bc = fmaf(wih[p], linb[p], bc);
    g_bcomb[g] = bc;
    if (g < 256) g_brz[g] = bc + dbhh[g];

    for (int kc = 0; kc < 32; ++kc) {
        float a4[4] = {0.f, 0.f, 0.f, 0.f};
#pragma unroll
        for (int p = 0; p < XDIM; ++p) {
            float wv = wih[p];
            const float* lp = linW + p * HDIM + kc * 4;
            a4[0] = fmaf(wv, lp[0], a4[0]);
            a4[1] = fmaf(wv, lp[1], a4[1]);
            a4[2] = fmaf(wv, lp[2], a4[2]);
            a4[3] = fmaf(wv, lp[3], a4[3]);
        }
        if (g < 256) {
            const float* d = dWhh + g * HDIM + kc * 4;
#pragma unroll
            for (int n = 0; n < 4; ++n) g_Wrz_rm[g * HDIM + kc * 4 + n] = a4[n] + d[n];
        } else {
#pragma unroll
            for (int n = 0; n < 4; ++n) g_Wcn_rm[(g - 256) * HDIM + kc * 4 + n] = a4[n];
        }
    }
}

// ---------------- int8 2-level quantization of all recurrence weights ----------------
__global__ void quant_kernel(const float* __restrict__ eWhh, const float* __restrict__ dWhh)
{
    int r = blockIdx.x * 128 + threadIdx.x;      // 0..895
    if (r >= GDIM + 512) return;

    const float* src;
    int8_t *dhi, *dlo;
    float* dal;
    int rr;
    if (r < GDIM) {
        src = eWhh + (size_t)r * HDIM;
        dhi = g_eW8hi + (size_t)r * HDIM; dlo = g_eW8lo + (size_t)r * HDIM;
        dal = g_ealpha + r;
    } else {
        rr = r - GDIM;
        src = (rr < 256) ? (g_Wrz_rm + (size_t)rr * HDIM)
            : (rr < 384) ? (dWhh + (size_t)rr * HDIM)
                         : (g_Wcn_rm + (size_t)(rr - 384) * HDIM);
        dhi = g_dW8hi + (size_t)rr * HDIM; dlo = g_dW8lo + (size_t)rr * HDIM;
        dal = g_dalpha + rr;
    }

    float mx = 0.f;
    for (int k = 0; k < HDIM; ++k) mx = fmaxf(mx, fabsf(src[k]));
    float alpha = (mx > 0.f) ? (mx / 127.f) : 1.f;
    float inva = 1.f / alpha;
    for (int k = 0; k < HDIM; ++k) {
        float ws = src[k] * inva;              // |ws| <= 127
        float q = rintf(ws);
        float l = rintf((ws - q) * 128.f);     // |l| <= 64
        dhi[k] = (int8_t)(int)q;
        dlo[k] = (int8_t)(int)l;
    }
    *dal = alpha * (1.f / 126.f);              // premultiplied by h scale
}

// ---------------- gi = x @ enc_Wih^T + enc_bih ----------------
__global__ __launch_bounds__(384) void gi_kernel(const float* __restrict__ x,
                                                 const float* __restrict__ wih,
                                                 const float* __restrict__ bih)
{
    __shared__ float xs[32 * XDIM];
    int tid = threadIdx.x;
    int r0  = blockIdx.x * 32;
    for (int i = tid; i < 32 * XDIM; i += 384) xs[i] = x[(size_t)r0 * XDIM + i];
    __syncthreads();

    float w[XDIM];
#pragma unroll
    for (int p = 0; p < XDIM; ++p) w[p] = wih[tid * XDIM + p];
    float bias = bih[tid];

    for (int b = 0; b < 32; ++b) {
        float acc = bias;
#pragma unroll
        for (int p = 0; p < XDIM; ++p) acc = fmaf(xs[b * XDIM + p], w[p], acc);
        int row = r0 + b;
        g_gi[((size_t)(row & 127) * NBATCH + (row >> 7)) * GDIM + tid] = acc;
    }
}

// quantize one h value into the int8 hi/lo B tiles
__device__ __forceinline__ void put_h(char* smem, uint32_t obhi, uint32_t oblo,
                                      int c, int j, float hv) {
    float hs = hv * 126.f;
    float q = rintf(hs);
    float l = rintf((hs - q) * 128.f);
    *(int8_t*)(smem + obhi + c * WSTR + j) = (int8_t)(int)q;
    *(int8_t*)(smem + oblo + c * WSTR + j) = (int8_t)(int)l;
}

// ---------------- encoder recurrence (int8 warp mma) ----------------
__global__ __launch_bounds__(512, 1) void enc_tc_kernel(const float* __restrict__ bhh)
{
    extern __shared__ char smem[];
    uint32_t sb = smem_u32(smem);
    int tid = threadIdx.x, wid = tid >> 5, lane = tid & 31;
    int b0 = blockIdx.x * TB;
    float* Gf  = (float*)(smem + E_G);
    float* hsm = (float*)(smem + E_H);

    // stage int8 weights (row stride 144)
    for (int w = tid; w < GDIM * 32; w += 512) {     // 32 words per row
        int row = w >> 5, kw = w & 31;
        *(uint32_t*)(smem + E_WHI + row * WSTR + kw * 4) = ((const uint32_t*)g_eW8hi)[w];
        *(uint32_t*)(smem + E_WLO + row * WSTR + kw * 4) = ((const uint32_t*)g_eW8lo)[w];
    }
    // zero h buffers
    for (int i = tid; i < TB * HDIM; i += 512) {
        hsm[i] = 0.f;
        int c = i >> 7, j = i & 127;
        *(int8_t*)(smem + E_BHI + c * WSTR + j) = 0;
        *(int8_t*)(smem + E_BLO + c * WSTR + j) = 0;
    }
    __syncthreads();

    // resident W_hi fragments + per-warp scales (warps 0-11: 32 gate rows each)
    uint32_t whi[2][4][4];
    float sa[4];
    uint32_t baseAhi = sb + E_WHI + (wid * 32 + (lane & 15)) * WSTR + (lane >> 4) * 16;
    uint32_t baseAlo = sb + E_WLO + (wid * 32 + (lane & 15)) * WSTR + (lane >> 4) * 16;
    int gq = lane >> 2, tig = lane & 3;
    if (wid < 12) {
#pragma unroll
        for (int m = 0; m < 2; ++m)
#pragma unroll
            for (int kc = 0; kc < 4; ++kc)
                LDSM4(whi[m][kc], baseAhi + m * 16 * WSTR + kc * 32);
#pragma unroll
        for (int q = 0; q < 4; ++q) sa[q] = g_ealpha[wid * 32 + q * 8 + gq];
    }

    int jj = tid & 127, c0 = tid >> 7;
    float bh_r = bhh[jj], bh_z = bhh[jj + 128], bh_n = bhh[jj + 256];
    uint32_t baseBh = sb + E_BHI + (lane & 15) * WSTR + (lane >> 4) * 16;
    uint32_t baseBl = sb + E_BLO + (lane & 15) * WSTR + (lane >> 4) * 16;
    __syncthreads();

    for (int t = 0; t < T_SEQ; ++t) {
        // prefetch gi (overlaps mma)
        float gir[4], giz[4], gin[4];
        const float* gp = g_gi + ((size_t)t * NBATCH + b0) * GDIM;
#pragma unroll
        for (int i = 0; i < 4; ++i) {
            int c = c0 + i * 4;
            gir[i] = gp[c * GDIM + jj];
            giz[i] = gp[c * GDIM + 128 + jj];
            gin[i] = gp[c * GDIM + 256 + jj];
        }

        if (wid < 12) {
            int a1[2][2][4], a2[2][2][4];
#pragma unroll
            for (int m = 0; m < 2; ++m)
#pragma unroll
                for (int n = 0; n < 2; ++n)
#pragma unroll
                    for (int q = 0; q < 4; ++q) { a1[m][n][q] = 0; a2[m][n][q] = 0; }

#pragma unroll
            for (int kc = 0; kc < 4; ++kc) {
                uint32_t bh[4], bl[4], wl0[4], wl1[4];
                LDSM4(bh, baseBh + kc * 32);        // bh[0],bh[2]: n0; bh[1],bh[3]: n1
                LDSM4(bl, baseBl + kc * 32);
                LDSM4(wl0, baseAlo + kc * 32);
                LDSM4(wl1, baseAlo + 16 * WSTR + kc * 32);
#pragma unroll
                for (int m = 0; m < 2; ++m) {
                    const uint32_t* wl = m ? wl1 : wl0;
#pragma unroll
                    for (int n = 0; n < 2; ++n) {
                        IMMA16832(a1[m][n], whi[m][kc], bh[n], bh[n + 2]);
                        IMMA16832(a2[m][n], whi[m][kc], bl[n], bl[n + 2]);
                        IMMA16832(a2[m][n], wl,         bh[n], bh[n + 2]);
                    }
                }
            }
            // dequant + write gates
#pragma unroll
            for (int m = 0; m < 2; ++m)
#pragma unroll
                for (int n = 0; n < 2; ++n) {
                    int row = wid * 32 + m * 16 + gq;
                    int col = n * 8 + 2 * tig;
                    float s0 = sa[m * 2], s1 = sa[m * 2 + 1];
                    Gf[row * GSTR + col]           = s0 * ((float)a1[m][n][0] + 0.0078125f * (float)a2[m][n][0]);
                    Gf[row * GSTR + col + 1]       = s0 * ((float)a1[m][n][1] + 0.0078125f * (float)a2[m][n][1]);
                    Gf[(row + 8) * GSTR + col]     = s1 * ((float)a1[m][n][2] + 0.0078125f * (float)a2[m][n][2]);
                    Gf[(row + 8) * GSTR + col + 1] = s1 * ((float)a1[m][n][3] + 0.0078125f * (float)a2[m][n][3]);
                }
        }
        __syncthreads();

#pragma unroll
        for (int i = 0; i < 4; ++i) {
            int c = c0 + i * 4;
            float r = sigf(gir[i] + bh_r + Gf[jj * GSTR + c]);
            float z = sigf(giz[i] + bh_z + Gf[(128 + jj) * GSTR + c]);
            float n = tanhf_(gin[i] + r * (Gf[(256 + jj) * GSTR + c] + bh_n));
            float h = hsm[c * HDIM + jj];
            float hv = n + z * (h - n);
            hsm[c * HDIM + jj] = hv;
            put_h(smem, E_BHI, E_BLO, c, jj, hv);
        }
        __syncthreads();
    }

#pragma unroll
    for (int i = 0; i < 4; ++i) {
        int c = c0 + i * 4;
        g_h0[(size_t)(b0 + c) * HDIM + jj] = hsm[c * HDIM + jj];
    }
}

// ---------------- decoder t=0 (plain FFMA) ----------------
__global__ __launch_bounds__(512, 1) void dec0_kernel(const float* __restrict__ dbih,
                                                      const float* __restrict__ dbhh)
{
    __shared__ float4 hs4[TB * 32];
    float* hs = (float*)hs4;
    int tid = threadIdx.x;
    int j = tid & 127, s = tid >> 7;
    int b0 = blockIdx.x * TB;

    for (int i = tid; i < TB * HDIM; i += 512) hs[i] = g_h0[(size_t)b0 * HDIM + i];
    float bi_r = dbih[j], bi_z = dbih[j + 128], bi_n = dbih[j + 256];
    __syncthreads();

    float ar[4] = {0, 0, 0, 0}, az[4] = {0, 0, 0, 0}, an[4] = {0, 0, 0, 0};
#pragma unroll 4
    for (int kc = 0; kc < 32; ++kc) {
        float4 wr = g_dWhh4[kc * GDIM + j];
        float4 wz = g_dWhh4[kc * GDIM + 128 + j];
        float4 wn = g_dWhh4[kc * GDIM + 256 + j];
#pragma unroll
        for (int nn = 0; nn < 4; ++nn) {
            float4 hv = hs4[(s + nn * 4) * 32 + kc];
            ar[nn] = fmaf(hv.x, wr.x, ar[nn]); ar[nn] = fmaf(hv.y, wr.y, ar[nn]);
            ar[nn] = fmaf(hv.z, wr.z, ar[nn]); ar[nn] = fmaf(hv.w, wr.w, ar[nn]);
            az[nn] = fmaf(hv.x, wz.x, az[nn]); az[nn] = fmaf(hv.y, wz.y, az[nn]);
            az[nn] = fmaf(hv.z, wz.z, az[nn]); az[nn] = fmaf(hv.w, wz.w, az[nn]);
            an[nn] = fmaf(hv.x, wn.x, an[nn]); an[nn] = fmaf(hv.y, wn.y, an[nn]);
            an[nn] = fmaf(hv.z, wn.z, an[nn]); an[nn] = fmaf(hv.w, wn.w, an[nn]);
        }
    }
    float bh_r = dbhh[j], bh_z = dbhh[j + 128], bh_n = dbhh[j + 256];
#pragma unroll
    for (int nn = 0; nn < 4; ++nn) {
        int b = s + nn * 4;
        float r = sigf(bi_r + bh_r + ar[nn]);
        float z = sigf(bi_z + bh_z + az[nn]);
        float n = tanhf_(bi_n + r * (an[nn] + bh_n));
        float h = hs[b * HDIM + j];
        float hv = n + z * (h - n);
        g_hall[((size_t)(b0 + b) * T_SEQ + 0) * HDIM + j] = hv;
        g_h1[(size_t)(b0 + b) * HDIM + j] = hv;
    }
}

// ---------------- decoder recurrence t=1..127 (int8 warp mma) ----------------
__global__ __launch_bounds__(512, 1) void dec_tc_kernel(const float* __restrict__ dbhh)
{
    extern __shared__ char smem[];
    uint32_t sb = smem_u32(smem);
    int tid = threadIdx.x, wid = tid >> 5, lane = tid & 31;
    int b0 = blockIdx.x * TB;
    float* Gf  = (float*)(smem + D_G);
    float* hsm = (float*)(smem + D_H);

    for (int w = tid; w < 512 * 32; w += 512) {
        int row = w >> 5, kw = w & 31;
        *(uint32_t*)(smem + D_WHI + row * WSTR + kw * 4) = ((const uint32_t*)g_dW8hi)[w];
        *(uint32_t*)(smem + D_WLO + row * WSTR + kw * 4) = ((const uint32_t*)g_dW8lo)[w];
    }
    for (int i = tid; i < TB * HDIM; i += 512) {
        int c = i >> 7, j = i & 127;
        float hv = g_h1[(size_t)(b0 + c) * HDIM + j];
        hsm[i] = hv;
        put_h(smem, D_BHI, D_BLO, c, j, hv);
    }
    __syncthreads();

    uint32_t whi[2][4][4];
    float sa[4];
    uint32_t baseAhi = sb + D_WHI + (wid * 32 + (lane & 15)) * WSTR + (lane >> 4) * 16;
    uint32_t baseAlo = sb + D_WLO + (wid * 32 + (lane & 15)) * WSTR + (lane >> 4) * 16;
    int gq = lane >> 2, tig = lane & 3;
#pragma unroll
    for (int m = 0; m < 2; ++m)
#pragma unroll
        for (int kc = 0; kc < 4; ++kc)
            LDSM4(whi[m][kc], baseAhi + m * 16 * WSTR + kc * 32);
#pragma unroll
    for (int q = 0; q < 4; ++q) sa[q] = g_dalpha[wid * 32 + q * 8 + gq];

    int jj = tid & 127, c0 = tid >> 7;
    float brz_r = g_brz[jj], brz_z = g_brz[jj + 128];
    float bcn = g_bcomb[jj + 256], bh_n = dbhh[jj + 256];
    uint32_t baseBh = sb + D_BHI + (lane & 15) * WSTR + (lane >> 4) * 16;
    uint32_t baseBl = sb + D_BLO + (lane & 15) * WSTR + (lane >> 4) * 16;
    __syncthreads();

    for (int tt = 0; tt < T_SEQ - 1; ++tt) {
        int a1[2][2][4], a2[2][2][4];
#pragma unroll
        for (int m = 0; m < 2; ++m)
#pragma unroll
            for (int n = 0; n < 2; ++n)
#pragma unroll
                for (int q = 0; q < 4; ++q) { a1[m][n][q] = 0; a2[m][n][q] = 0; }

#pragma unroll
        for (int kc = 0; kc < 4; ++kc) {
            uint32_t bh[4], bl[4], wl0[4], wl1[4];
            LDSM4(bh, baseBh + kc * 32);
            LDSM4(bl, baseBl + kc * 32);
            LDSM4(wl0, baseAlo + kc * 32);
            LDSM4(wl1, baseAlo + 16 * WSTR + kc * 32);
#pragma unroll
            for (int m = 0; m < 2; ++m) {
                const uint32_t* wl = m ? wl1 : wl0;
#pragma unroll
                for (int n = 0; n < 2; ++n) {
                    IMMA16832(a1[m][n], whi[m][kc], bh[n], bh[n + 2]);
                    IMMA16832(a2[m][n], whi[m][kc], bl[n], bl[n + 2]);
                    IMMA16832(a2[m][n], wl,         bh[n], bh[n + 2]);
                }
            }
        }
#pragma unroll
        for (int m = 0; m < 2; ++m)
#pragma unroll
            for (int n = 0; n < 2; ++n) {
                int row = wid * 32 + m * 16 + gq;
                int col = n * 8 + 2 * tig;
                float s0 = sa[m * 2], s1 = sa[m * 2 + 1];
                Gf[row * GSTR + col]           = s0 * ((float)a1[m][n][0] + 0.0078125f * (float)a2[m][n][0]);
                Gf[row * GSTR + col + 1]       = s0 * ((float)a1[m][n][1] + 0.0078125f * (float)a2[m][n][1]);
                Gf[(row + 8) * GSTR + col]     = s1 * ((float)a1[m][n][2] + 0.0078125f * (float)a2[m][n][2]);
                Gf[(row + 8) * GSTR + col + 1] = s1 * ((float)a1[m][n][3] + 0.0078125f * (float)a2[m][n][3]);
            }
        __syncthreads();

#pragma unroll
        for (int i = 0; i < 4; ++i) {
            int c = c0 + i * 4;
            float r = sigf(brz_r + Gf[jj * GSTR + c]);
            float z = sigf(brz_z + Gf[(128 + jj) * GSTR + c]);
            float n = tanhf_(bcn + Gf[(384 + jj) * GSTR + c]
                             + r * (Gf[(256 + jj) * GSTR + c] + bh_n));
            float h = hsm[c * HDIM + jj];
            float hv = n + z * (h - n);
            hsm[c * HDIM + jj] = hv;
            g_hall[((size_t)(b0 + c) * T_SEQ + tt + 1) * HDIM + jj] = hv;
            put_h(smem, D_BHI, D_BLO, c, jj, hv);
        }
        __syncthreads();
    }
}

// ---------------- out = g_hall @ lin_W^T + lin_b ----------------
__global__ void out_kernel(const float* __restrict__ linW, const float* __restrict__ linb,
                           float* __restrict__ out)
{
    __shared__ float hS[16 * HDIM];
    __shared__ float lS[HDIM * XDIM];
    int tx = threadIdx.x, ty = threadIdx.y;
    int tid = ty * XDIM + tx;
    int nthr = XDIM * 16;
    size_t r0 = (size_t)blockIdx.x * 16;

    for (int i = tid; i < 16 * HDIM; i += nthr) hS[i] = g_hall[r0 * HDIM + i];
    for (int i = tid; i < HDIM * XDIM; i += nthr) {
        int k = i / XDIM, p = i - k * XDIM;
        lS[i] = linW[p * HDIM + k];
    }
    __syncthreads();

    float acc = linb[tx];
    const float* hrow = hS + ty * HDIM;
#pragma unroll 8
    for (int k = 0; k < HDIM; ++k) acc = fmaf(hrow[k], lS[k * XDIM + tx], acc);
    out[(r0 + ty) * XDIM + tx] = acc;
}

// ---------------- launch ----------------
extern "C" void kernel_launch(void* const* d_in, const int* in_sizes, int n_in,
                              void* d_out, int out_size) {
    const float* x        = (const float*)d_in[0];
    const float* enc_Wih  = (const float*)d_in[1];
    const float* enc_Whh  = (const float*)d_in[2];
    const float* enc_bih  = (const float*)d_in[3];
    const float* enc_bhh  = (const float*)d_in[4];
    const float* dec_Wih  = (const float*)d_in[5];
    const float* dec_Whh  = (const float*)d_in[6];
    const float* dec_bih  = (const float*)d_in[7];
    const float* dec_bhh  = (const float*)d_in[8];
    const float* lin_W    = (const float*)d_in[9];
    const float* lin_b    = (const float*)d_in[10];
    float* out = (float*)d_out;

    cudaFuncSetAttribute(enc_tc_kernel, cudaFuncAttributeMaxDynamicSharedMemorySize, E_SZ);
    cudaFuncSetAttribute(dec_tc_kernel, cudaFuncAttributeMaxDynamicSharedMemorySize, D_SZ);

    prep_kernel<<<3, 128>>>(dec_Whh, dec_Wih, lin_W, lin_b, dec_bih, dec_bhh);
    quant_kernel<<<7, 128>>>(enc_Whh, dec_Whh);
    gi_kernel<<<(T_SEQ * NBATCH) / 32, 384>>>(x, enc_Wih, enc_bih);
    enc_tc_kernel<<<NBATCH / TB, 512, E_SZ>>>(enc_bhh);
    dec0_kernel<<<NBATCH / TB, 512>>>(dec_bih, dec_bhh);
    dec_tc_kernel<<<NBATCH / TB, 512, D_SZ>>>(dec_bhh);
    out_kernel<<<(NBATCH * T_SEQ) / 16, dim3(XDIM, 16)>>>(lin_W, lin_b, out);
}

// round 8
// speedup vs baseline: 1.4839x; 1.4839x over previous
#include <cuda_runtime.h>
#include <cuda_bf16.h>
#include <cstdint>

#define T_SEQ 128
#define NBATCH 2048
#define HDIM  128
#define GDIM  384
#define XDIM  38
#define TB    16

// ---------------- device scratch ----------------
__device__ float   g_gi[(size_t)T_SEQ * NBATCH * GDIM];
__device__ float   g_hall[(size_t)NBATCH * T_SEQ * HDIM];  // [b][t][j]
__device__ float   g_h0[(size_t)NBATCH * HDIM];
__device__ float   g_h1[(size_t)NBATCH * HDIM];
__device__ float4  g_dWhh4[32 * GDIM];
__device__ float   g_Wrz_rm[256 * HDIM];
__device__ float   g_Wcn_rm[128 * HDIM];
__device__ float   g_bcomb[GDIM];
__device__ float   g_brz[256];

__device__ __forceinline__ float sigf(float x)  { return __fdividef(1.f, 1.f + __expf(-x)); }
__device__ __forceinline__ float tanhf_(float x){ return __fdividef(2.f, 1.f + __expf(-2.f * x)) - 1.f; }

__device__ __forceinline__ uint32_t smem_u32(const void* p) {
    uint32_t a;
    asm("{ .reg .u64 t; cvta.to.shared.u64 t, %1; cvt.u32.u64 %0, t; }" : "=r"(a) : "l"(p));
    return a;
}

#define LDSM4(r, a) \
    asm volatile("ldmatrix.sync.aligned.m8n8.x4.shared.b16 {%0,%1,%2,%3}, [%4];" \
        : "=r"((r)[0]), "=r"((r)[1]), "=r"((r)[2]), "=r"((r)[3]) : "r"(a))

#define MMA16816(d, a, b0, b1) \
    asm volatile("mma.sync.aligned.m16n8k16.row.col.f32.bf16.bf16.f32 " \
        "{%0,%1,%2,%3}, {%4,%5,%6,%7}, {%8,%9}, {%0,%1,%2,%3};" \
        : "+f"((d)[0]), "+f"((d)[1]), "+f"((d)[2]), "+f"((d)[3]) \
        : "r"((a)[0]), "r"((a)[1]), "r"((a)[2]), "r"((a)[3]), "r"(b0), "r"(b1))

#define WSTR 272
#define GSTR 17

// enc smem map
#define E_W   0              // 384*272 = 104448 (Whi staged, then overwritten by Wlo)
#define E_G   104448         // 384*17*4 = 26112
#define E_BHI 130560         // 16*272
#define E_BLO 134912
#define E_SZ  139264
// dec smem map
#define D_W   0              // 512*272 = 139264
#define D_G   139264         // 512*17*4 = 34816
#define D_BHI 174080
#define D_BLO 178432
#define D_SZ  182784

// ---------------- weight prep ----------------
__global__ void prep_kernel(const float* __restrict__ dWhh,
                            const float* __restrict__ dWih, const float* __restrict__ linW,
                            const float* __restrict__ linb, const float* __restrict__ dbih,
                            const float* __restrict__ dbhh)
{
    int g = blockIdx.x * 128 + threadIdx.x;
    if (g >= GDIM) return;

    for (int kc = 0; kc < 32; ++kc) {
        const float* d = dWhh + g * HDIM + kc * 4;
        g_dWhh4[kc * GDIM + g] = make_float4(d[0], d[1], d[2], d[3]);
    }

    float wih[XDIM];
#pragma unroll
    for (int p = 0; p < XDIM; ++p) wih[p] = dWih[g * XDIM + p];

    float bc = dbih[g];
#pragma unroll
    for (int p = 0; p < XDIM; ++p) bc = fmaf(wih[p], linb[p], bc);
    g_bcomb[g] = bc;
    if (g < 256) g_brz[g] = bc + dbhh[g];

    for (int kc = 0; kc < 32; ++kc) {
        float a4[4] = {0.f, 0.f, 0.f, 0.f};
#pragma unroll
        for (int p = 0; p < XDIM; ++p) {
            float wv = wih[p];
            const float* lp = linW + p * HDIM + kc * 4;
            a4[0] = fmaf(wv, lp[0], a4[0]);
            a4[1] = fmaf(wv, lp[1], a4[1]);
            a4[2] = fmaf(wv, lp[2], a4[2]);
            a4[3] = fmaf(wv, lp[3], a4[3]);
        }
        if (g < 256) {
            const float* d = dWhh + g * HDIM + kc * 4;
#pragma unroll
            for (int n = 0; n < 4; ++n) g_Wrz_rm[g * HDIM + kc * 4 + n] = a4[n] + d[n];
        } else {
#pragma unroll
            for (int n = 0; n < 4; ++n) g_Wcn_rm[(g - 256) * HDIM + kc * 4 + n] = a4[n];
        }
    }
}

// ---------------- gi = x @ enc_Wih^T + enc_bih ----------------
__global__ __launch_bounds__(384) void gi_kernel(const float* __restrict__ x,
                                                 const float* __restrict__ wih,
                                                 const float* __restrict__ bih)
{
    __shared__ float xs[32 * XDIM];
    int tid = threadIdx.x;
    int r0  = blockIdx.x * 32;
    for (int i = tid; i < 32 * XDIM; i += 384) xs[i] = x[(size_t)r0 * XDIM + i];
    __syncthreads();

    float w[XDIM];
#pragma unroll
    for (int p = 0; p < XDIM; ++p) w[p] = wih[tid * XDIM + p];
    float bias = bih[tid];

    for (int b = 0; b < 32; ++b) {
        float acc = bias;
#pragma unroll
        for (int p = 0; p < XDIM; ++p) acc = fmaf(xs[b * XDIM + p], w[p], acc);
        int row = r0 + b;
        g_gi[((size_t)(row & 127) * NBATCH + (row >> 7)) * GDIM + tid] = acc;
    }
}

// stage bf16 hi or lo of W (row-major src) into smem (stride 272B)
__device__ __forceinline__ void stage_w(char* smem, const float* src, int row, int k, bool lo) {
    float w = src[k];
    __nv_bfloat16 hb = __float2bfloat16_rn(w);
    __nv_bfloat16 v = lo ? __float2bfloat16_rn(w - __bfloat162float(hb)) : hb;
    *(__nv_bfloat16*)(smem + row * WSTR + k * 2) = v;
}
// write h hi/lo bf16 tiles at (c, j)
__device__ __forceinline__ void put_h(char* smem, uint32_t obhi, uint32_t oblo,
                                      int c, int j, float hv) {
    __nv_bfloat16 hb = __float2bfloat16_rn(hv);
    *(__nv_bfloat16*)(smem + obhi + c * WSTR + j * 2) = hb;
    *(__nv_bfloat16*)(smem + oblo + c * WSTR + j * 2) =
        __float2bfloat16_rn(hv - __bfloat162float(hb));
}

// ---------------- encoder recurrence (pipelined bf16 mma) ----------------
__global__ __launch_bounds__(512, 1) void enc_tc_kernel(const float* __restrict__ eWhh,
                                                        const float* __restrict__ bhh)
{
    extern __shared__ char smem[];
    uint32_t sb = smem_u32(smem);
    int tid = threadIdx.x, wid = tid >> 5, lane = tid & 31;
    int b0 = blockIdx.x * TB;
    float* Gf = (float*)(smem + E_G);

    // stage W_hi
    for (int i = tid; i < GDIM * HDIM; i += 512)
        stage_w(smem + E_W, eWhh + (i >> 7) * HDIM, i >> 7, i & 127, false);
    __syncthreads();

    uint32_t whi[2][8][4];
    uint32_t baseA = sb + E_W + (wid * 32 + (lane & 15)) * WSTR + (lane >> 4) * 16;
    if (wid < 12) {
#pragma unroll
        for (int m = 0; m < 2; ++m)
#pragma unroll
            for (int kc = 0; kc < 8; ++kc)
                LDSM4(whi[m][kc], baseA + m * 16 * WSTR + kc * 32);
    }
    __syncthreads();

    // stage W_lo over same region; zero h tiles
    for (int i = tid; i < GDIM * HDIM; i += 512)
        stage_w(smem + E_W, eWhh + (i >> 7) * HDIM, i >> 7, i & 127, true);
    for (int i = tid; i < TB * HDIM; i += 512) {
        int c = i >> 7, j = i & 127;
        *(__nv_bfloat16*)(smem + E_BHI + c * WSTR + j * 2) = __float2bfloat16_rn(0.f);
        *(__nv_bfloat16*)(smem + E_BLO + c * WSTR + j * 2) = __float2bfloat16_rn(0.f);
    }

    int jj = tid & 127, cb = (tid >> 7) * 2;
    float bh_r = bhh[jj], bh_z = bhh[jj + 128], bh_n = bhh[jj + 256];
    uint32_t baseBh = sb + E_BHI + (lane & 7) * WSTR + (lane >> 3) * 16;
    uint32_t baseBl = sb + E_BLO + (lane & 7) * WSTR + (lane >> 3) * 16;
    int gq = lane >> 2, tig = lane & 3;
    float hreg[2][2] = {{0.f, 0.f}, {0.f, 0.f}};
    float pAr[2], pAz[2], pAn[2], pBr[2], pBz[2], pBn[2];

    // mma for one column group; writes this warp's G rows for that group
#define ENC_MMA(g)                                                                   \
    do {                                                                             \
        float d[2][4];                                                               \
        for (int m = 0; m < 2; ++m)                                                  \
            for (int q = 0; q < 4; ++q) d[m][q] = 0.f;                               \
        uint32_t goff = (g) * 8 * WSTR;                                              \
        _Pragma("unroll")                                                            \
        for (int kp = 0; kp < 4; ++kp) {                                             \
            uint32_t bhv[4], blv[4];                                                 \
            LDSM4(bhv, baseBh + goff + kp * 64);                                     \
            LDSM4(blv, baseBl + goff + kp * 64);                                     \
            _Pragma("unroll")                                                        \
            for (int ch = 0; ch < 2; ++ch) {                                         \
                int kc = kp * 2 + ch;                                                \
                uint32_t al[2][4];                                                   \
                LDSM4(al[0], baseA + kc * 32);                                       \
                LDSM4(al[1], baseA + 16 * WSTR + kc * 32);                           \
                _Pragma("unroll")                                                    \
                for (int m = 0; m < 2; ++m) {                                        \
                    MMA16816(d[m], whi[m][kc], bhv[2 * ch], bhv[2 * ch + 1]);        \
                    MMA16816(d[m], whi[m][kc], blv[2 * ch], blv[2 * ch + 1]);        \
                    MMA16816(d[m], al[m],      bhv[2 * ch], bhv[2 * ch + 1]);        \
                }                                                                    \
            }                                                                        \
        }                                                                            \
        _Pragma("unroll")                                                            \
        for (int m = 0; m < 2; ++m) {                                                \
            int row = wid * 32 + m * 16 + gq;                                        \
            int col = (g) * 8 + 2 * tig;                                             \
            Gf[row * GSTR + col]           = d[m][0];                                \
            Gf[row * GSTR + col + 1]       = d[m][1];                                \
            Gf[(row + 8) * GSTR + col]     = d[m][2];                                \
            Gf[(row + 8) * GSTR + col + 1] = d[m][3];                                \
        }                                                                            \
    } while (0)

#define ENC_PREF(g, t, pr, pz, pn)                                                   \
    do {                                                                             \
        const float* gp = g_gi + ((size_t)(t) * NBATCH + b0) * GDIM;                 \
        _Pragma("unroll")                                                            \
        for (int i = 0; i < 2; ++i) {                                                \
            int c = (g) * 8 + cb + i;                                                \
            pr[i] = gp[c * GDIM + jj];                                               \
            pz[i] = gp[c * GDIM + 128 + jj];                                         \
            pn[i] = gp[c * GDIM + 256 + jj];                                         \
        }                                                                            \
    } while (0)

#define ENC_EPI(g, pr, pz, pn)                                                       \
    do {                                                                             \
        _Pragma("unroll")                                                            \
        for (int i = 0; i < 2; ++i) {                                                \
            int c = (g) * 8 + cb + i;                                                \
            float r = sigf(pr[i] + bh_r + Gf[jj * GSTR + c]);                        \
            float z = sigf(pz[i] + bh_z + Gf[(128 + jj) * GSTR + c]);                \
            float n = tanhf_(pn[i] + r * (Gf[(256 + jj) * GSTR + c] + bh_n));        \
            float h = hreg[g][i];                                                    \
            float hv = n + z * (h - n);                                              \
            hreg[g][i] = hv;                                                         \
            put_h(smem, E_BHI, E_BLO, c, jj, hv);                                    \
        }                                                                            \
    } while (0)

    ENC_PREF(0, 0, pAr, pAz, pAn);
    __syncthreads();
    if (wid < 12) ENC_MMA(0);
    __syncthreads();

    for (int t = 0; t < T_SEQ; ++t) {
        // P1: mma B(t) || epi A(t)
        ENC_PREF(1, t, pBr, pBz, pBn);
        if (wid < 12) ENC_MMA(1);
        ENC_EPI(0, pAr, pAz, pAn);
        __syncthreads();
        // P2: mma A(t+1) || epi B(t)
        if (t + 1 < T_SEQ) {
            ENC_PREF(0, t + 1, pAr, pAz, pAn);
            if (wid < 12) ENC_MMA(0);
        }
        ENC_EPI(1, pBr, pBz, pBn);
        __syncthreads();
    }

#pragma unroll
    for (int g = 0; g < 2; ++g)
#pragma unroll
        for (int i = 0; i < 2; ++i) {
            int c = g * 8 + cb + i;
            g_h0[(size_t)(b0 + c) * HDIM + jj] = hreg[g][i];
        }
}

// ---------------- decoder t=0 (plain FFMA) ----------------
__global__ __launch_bounds__(512, 1) void dec0_kernel(const float* __restrict__ dbih,
                                                      const float* __restrict__ dbhh)
{
    __shared__ float4 hs4[TB * 32];
    float* hs = (float*)hs4;
    int tid = threadIdx.x;
    int j = tid & 127, s = tid >> 7;
    int b0 = blockIdx.x * TB;

    for (int i = tid; i < TB * HDIM; i += 512) hs[i] = g_h0[(size_t)b0 * HDIM + i];
    float bi_r = dbih[j], bi_z = dbih[j + 128], bi_n = dbih[j + 256];
    __syncthreads();

    float ar[4] = {0, 0, 0, 0}, az[4] = {0, 0, 0, 0}, an[4] = {0, 0, 0, 0};
#pragma unroll 4
    for (int kc = 0; kc < 32; ++kc) {
        float4 wr = g_dWhh4[kc * GDIM + j];
        float4 wz = g_dWhh4[kc * GDIM + 128 + j];
        float4 wn = g_dWhh4[kc * GDIM + 256 + j];
#pragma unroll
        for (int nn = 0; nn < 4; ++nn) {
            float4 hv = hs4[(s + nn * 4) * 32 + kc];
            ar[nn] = fmaf(hv.x, wr.x, ar[nn]); ar[nn] = fmaf(hv.y, wr.y, ar[nn]);
            ar[nn] = fmaf(hv.z, wr.z, ar[nn]); ar[nn] = fmaf(hv.w, wr.w, ar[nn]);
            az[nn] = fmaf(hv.x, wz.x, az[nn]); az[nn] = fmaf(hv.y, wz.y, az[nn]);
            az[nn] = fmaf(hv.z, wz.z, az[nn]); az[nn] = fmaf(hv.w, wz.w, az[nn]);
            an[nn] = fmaf(hv.x, wn.x, an[nn]); an[nn] = fmaf(hv.y, wn.y, an[nn]);
            an[nn] = fmaf(hv.z, wn.z, an[nn]); an[nn] = fmaf(hv.w, wn.w, an[nn]);
        }
    }
    float bh_r = dbhh[j], bh_z = dbhh[j + 128], bh_n = dbhh[j + 256];
#pragma unroll
    for (int nn = 0; nn < 4; ++nn) {
        int b = s + nn * 4;
        float r = sigf(bi_r + bh_r + ar[nn]);
        float z = sigf(bi_z + bh_z + az[nn]);
        float n = tanhf_(bi_n + r * (an[nn] + bh_n));
        float h = hs[b * HDIM + j];
        float hv = n + z * (h - n);
        g_hall[((size_t)(b0 + b) * T_SEQ + 0) * HDIM + j] = hv;
        g_h1[(size_t)(b0 + b) * HDIM + j] = hv;
    }
}

// ---------------- decoder recurrence t=1..127 (pipelined bf16 mma) ----------------
__global__ __launch_bounds__(512, 1) void dec_tc_kernel(const float* __restrict__ dWhh,
                                                        const float* __restrict__ dbhh)
{
    extern __shared__ char smem[];
    uint32_t sb = smem_u32(smem);
    int tid = threadIdx.x, wid = tid >> 5, lane = tid & 31;
    int b0 = blockIdx.x * TB;
    float* Gf = (float*)(smem + D_G);

    // stage W_hi (rows 0-255 Wrz, 256-383 dWhh n, 384-511 Wcn)
    for (int i = tid; i < 512 * HDIM; i += 512) {
        int row = i >> 7, k = i & 127;
        const float* src = (row < 256) ? (g_Wrz_rm + (size_t)row * HDIM)
                        : (row < 384) ? (dWhh + (size_t)row * HDIM)
                                      : (g_Wcn_rm + (size_t)(row - 384) * HDIM);
        stage_w(smem + D_W, src, row, k, false);
    }
    __syncthreads();

    uint32_t whi[2][8][4];
    uint32_t baseA = sb + D_W + (wid * 32 + (lane & 15)) * WSTR + (lane >> 4) * 16;
#pragma unroll
    for (int m = 0; m < 2; ++m)
#pragma unroll
        for (int kc = 0; kc < 8; ++kc)
            LDSM4(whi[m][kc], baseA + m * 16 * WSTR + kc * 32);
    __syncthreads();

    // stage W_lo + h1 tiles
    for (int i = tid; i < 512 * HDIM; i += 512) {
        int row = i >> 7, k = i & 127;
        const float* src = (row < 256) ? (g_Wrz_rm + (size_t)row * HDIM)
                        : (row < 384) ? (dWhh + (size_t)row * HDIM)
                                      : (g_Wcn_rm + (size_t)(row - 384) * HDIM);
        stage_w(smem + D_W, src, row, k, true);
    }
    int jj = tid & 127, cb = (tid >> 7) * 2;
    float hreg[2][2];
#pragma unroll
    for (int g = 0; g < 2; ++g)
#pragma unroll
        for (int i = 0; i < 2; ++i) {
            int c = g * 8 + cb + i;
            float hv = g_h1[(size_t)(b0 + c) * HDIM + jj];
            hreg[g][i] = hv;
            put_h(smem, D_BHI, D_BLO, c, jj, hv);
        }

    float brz_r = g_brz[jj], brz_z = g_brz[jj + 128];
    float bcn = g_bcomb[jj + 256], bh_n = dbhh[jj + 256];
    uint32_t baseBh = sb + D_BHI + (lane & 7) * WSTR + (lane >> 3) * 16;
    uint32_t baseBl = sb + D_BLO + (lane & 7) * WSTR + (lane >> 3) * 16;
    int gq = lane >> 2, tig = lane & 3;

#define DEC_MMA(g)                                                                   \
    do {                                                                             \
        float d[2][4];                                                               \
        for (int m = 0; m < 2; ++m)                                                  \
            for (int q = 0; q < 4; ++q) d[m][q] = 0.f;                               \
        uint32_t goff = (g) * 8 * WSTR;                                              \
        _Pragma("unroll")                                                            \
        for (int kp = 0; kp < 4; ++kp) {                                             \
            uint32_t bhv[4], blv[4];                                                 \
            LDSM4(bhv, baseBh + goff + kp * 64);                                     \
            LDSM4(blv, baseBl + goff + kp * 64);                                     \
            _Pragma("unroll")                                                        \
            for (int ch = 0; ch < 2; ++ch) {                                         \
                int kc = kp * 2 + ch;                                                \
                uint32_t al[2][4];                                                   \
                LDSM4(al[0], baseA + kc * 32);                                       \
                LDSM4(al[1], baseA + 16 * WSTR + kc * 32);                           \
                _Pragma("unroll")                                                    \
                for (int m = 0; m < 2; ++m) {                                        \
                    MMA16816(d[m], whi[m][kc], bhv[2 * ch], bhv[2 * ch + 1]);        \
                    MMA16816(d[m], whi[m][kc], blv[2 * ch], blv[2 * ch + 1]);        \
                    MMA16816(d[m], al[m],      bhv[2 * ch], bhv[2 * ch + 1]);        \
                }                                                                    \
            }                                                                        \
        }                                                                            \
        _Pragma("unroll")                                                            \
        for (int m = 0; m < 2; ++m) {                                                \
            int row = wid * 32 + m * 16 + gq;                                        \
            int col = (g) * 8 + 2 * tig;                                             \
            Gf[row * GSTR + col]           = d[m][0];                                \
            Gf[row * GSTR + col + 1]       = d[m][1];                                \
            Gf[(row + 8) * GSTR + col]     = d[m][2];                                \
            Gf[(row + 8) * GSTR + col + 1] = d[m][3];                                \
        }                                                                            \
    } while (0)

#define DEC_EPI(g, tt)                                                               \
    do {                                                                             \
        _Pragma("unroll")                                                            \
        for (int i = 0; i < 2; ++i) {                                                \
            int c = (g) * 8 + cb + i;                                                \
            float r = sigf(brz_r + Gf[jj * GSTR + c]);                               \
            float z = sigf(brz_z + Gf[(128 + jj) * GSTR + c]);                       \
            float n = tanhf_(bcn + Gf[(384 + jj) * GSTR + c]                         \
                             + r * (Gf[(256 + jj) * GSTR + c] + bh_n));              \
            float h = hreg[g][i];                                                    \
            float hv = n + z * (h - n);                                              \
            hreg[g][i] = hv;                                                         \
            g_hall[((size_t)(b0 + c) * T_SEQ + (tt) + 1) * HDIM + jj] = hv;          \
            put_h(smem, D_BHI, D_BLO, c, jj, hv);                                    \
        }                                                                            \
    } while (0)

    __syncthreads();
    DEC_MMA(0);
    __syncthreads();

    for (int tt = 0; tt < T_SEQ - 1; ++tt) {
        DEC_MMA(1);
        DEC_EPI(0, tt);
        __syncthreads();
        if (tt + 1 < T_SEQ - 1) DEC_MMA(0);
        DEC_EPI(1, tt);
        __syncthreads();
    }
}

// ---------------- out = g_hall @ lin_W^T + lin_b ----------------
__global__ void out_kernel(const float* __restrict__ linW, const float* __restrict__ linb,
                           float* __restrict__ out)
{
    __shared__ float hS[16 * HDIM];
    __shared__ float lS[HDIM * XDIM];
    int tx = threadIdx.x, ty = threadIdx.y;
    int tid = ty * XDIM + tx;
    int nthr = XDIM * 16;
    size_t r0 = (size_t)blockIdx.x * 16;

    for (int i = tid; i < 16 * HDIM; i += nthr) hS[i] = g_hall[r0 * HDIM + i];
    for (int i = tid; i < HDIM * XDIM; i += nthr) {
        int k = i / XDIM, p = i - k * XDIM;
        lS[i] = linW[p * HDIM + k];
    }
    __syncthreads();

    float acc = linb[tx];
    const float* hrow = hS + ty * HDIM;
#pragma unroll 8
    for (int k = 0; k < HDIM; ++k) acc = fmaf(hrow[k], lS[k * XDIM + tx], acc);
    out[(r0 + ty) * XDIM + tx] = acc;
}

// ---------------- launch ----------------
extern "C" void kernel_launch(void* const* d_in, const int* in_sizes, int n_in,
                              void* d_out, int out_size) {
    const float* x        = (const float*)d_in[0];
    const float* enc_Wih  = (const float*)d_in[1];
    const float* enc_Whh  = (const float*)d_in[2];
    const float* enc_bih  = (const float*)d_in[3];
    const float* enc_bhh  = (const float*)d_in[4];
    const float* dec_Wih  = (const float*)d_in[5];
    const float* dec_Whh  = (const float*)d_in[6];
    const float* dec_bih  = (const float*)d_in[7];
    const float* dec_bhh  = (const float*)d_in[8];
    const float* lin_W    = (const float*)d_in[9];
    const float* lin_b    = (const float*)d_in[10];
    float* out = (float*)d_out;

    cudaFuncSetAttribute(enc_tc_kernel, cudaFuncAttributeMaxDynamicSharedMemorySize, E_SZ);
    cudaFuncSetAttribute(dec_tc_kernel, cudaFuncAttributeMaxDynamicSharedMemorySize, D_SZ);

    prep_kernel<<<3, 128>>>(dec_Whh, dec_Wih, lin_W, lin_b, dec_bih, dec_bhh);
    gi_kernel<<<(T_SEQ * NBATCH) / 32, 384>>>(x, enc_Wih, enc_bih);
    enc_tc_kernel<<<NBATCH / TB, 512, E_SZ>>>(enc_Whh, enc_bhh);
    dec0_kernel<<<NBATCH / TB, 512>>>(dec_bih, dec_bhh);
    dec_tc_kernel<<<NBATCH / TB, 512, D_SZ>>>(dec_Whh, dec_bhh);
    out_kernel<<<(NBATCH * T_SEQ) / 16, dim3(XDIM, 16)>>>(lin_W, lin_b, out);
}

// round 9
// speedup vs baseline: 1.6869x; 1.1368x over previous
#include <cuda_runtime.h>
#include <cuda_fp16.h>
#include <cstdint>

#define T_SEQ 128
#define NBATCH 2048
#define HDIM  128
#define GDIM  384
#define XDIM  38
#define TB    16

// ---------------- device scratch ----------------
__device__ float   g_gi[(size_t)T_SEQ * NBATCH * GDIM];
__device__ float   g_hall[(size_t)NBATCH * T_SEQ * HDIM];  // [b][t][j]
__device__ float   g_h0[(size_t)NBATCH * HDIM];
__device__ float   g_h1[(size_t)NBATCH * HDIM];
__device__ float4  g_dWhh4[32 * GDIM];
__device__ float   g_Wrz_rm[256 * HDIM];
__device__ float   g_Wcn_rm[128 * HDIM];
__device__ float   g_bcomb[GDIM];
__device__ float   g_brz[256];

__device__ __forceinline__ float sigf(float x)  { return __fdividef(1.f, 1.f + __expf(-x)); }
__device__ __forceinline__ float tanhf_(float x){ return __fdividef(2.f, 1.f + __expf(-2.f * x)) - 1.f; }

__device__ __forceinline__ uint32_t smem_u32(const void* p) {
    uint32_t a;
    asm("{ .reg .u64 t; cvta.to.shared.u64 t, %1; cvt.u32.u64 %0, t; }" : "=r"(a) : "l"(p));
    return a;
}

#define LDSM4(r, a) \
    asm volatile("ldmatrix.sync.aligned.m8n8.x4.shared.b16 {%0,%1,%2,%3}, [%4];" \
        : "=r"((r)[0]), "=r"((r)[1]), "=r"((r)[2]), "=r"((r)[3]) : "r"(a))

#define MMA16816(d, a, b0, b1) \
    asm volatile("mma.sync.aligned.m16n8k16.row.col.f32.f16.f16.f32 " \
        "{%0,%1,%2,%3}, {%4,%5,%6,%7}, {%8,%9}, {%0,%1,%2,%3};" \
        : "+f"((d)[0]), "+f"((d)[1]), "+f"((d)[2]), "+f"((d)[3]) \
        : "r"((a)[0]), "r"((a)[1]), "r"((a)[2]), "r"((a)[3]), "r"(b0), "r"(b1))

#define WSTR 272
#define GSTR 17

// enc smem map
#define E_W   0              // 384*272
#define E_G   104448         // 384*17*4
#define E_BHI 130560         // 16*272
#define E_BLO 134912
#define E_SZ  139264
// dec smem map
#define D_W   0              // 512*272
#define D_G   139264         // 512*17*4
#define D_BHI 174080
#define D_BLO 178432
#define D_SZ  182784

// ---------------- weight prep ----------------
__global__ void prep_kernel(const float* __restrict__ dWhh,
                            const float* __restrict__ dWih, const float* __restrict__ linW,
                            const float* __restrict__ linb, const float* __restrict__ dbih,
                            const float* __restrict__ dbhh)
{
    int g = blockIdx.x * 128 + threadIdx.x;
    if (g >= GDIM) return;

    for (int kc = 0; kc < 32; ++kc) {
        const float* d = dWhh + g * HDIM + kc * 4;
        g_dWhh4[kc * GDIM + g] = make_float4(d[0], d[1], d[2], d[3]);
    }

    float wih[XDIM];
#pragma unroll
    for (int p = 0; p < XDIM; ++p) wih[p] = dWih[g * XDIM + p];

    float bc = dbih[g];
#pragma unroll
    for (int p = 0; p < XDIM; ++p) bc = fmaf(wih[p], linb[p], bc);
    g_bcomb[g] = bc;
    if (g < 256) g_brz[g] = bc + dbhh[g];

    for (int kc = 0; kc < 32; ++kc) {
        float a4[4] = {0.f, 0.f, 0.f, 0.f};
#pragma unroll
        for (int p = 0; p < XDIM; ++p) {
            float wv = wih[p];
            const float* lp = linW + p * HDIM + kc * 4;
            a4[0] = fmaf(wv, lp[0], a4[0]);
            a4[1] = fmaf(wv, lp[1], a4[1]);
            a4[2] = fmaf(wv, lp[2], a4[2]);
            a4[3] = fmaf(wv, lp[3], a4[3]);
        }
        if (g < 256) {
            const float* d = dWhh + g * HDIM + kc * 4;
#pragma unroll
            for (int n = 0; n < 4; ++n) g_Wrz_rm[g * HDIM + kc * 4 + n] = a4[n] + d[n];
        } else {
#pragma unroll
            for (int n = 0; n < 4; ++n) g_Wcn_rm[(g - 256) * HDIM + kc * 4 + n] = a4[n];
        }
    }
}

// ---------------- gi = x @ enc_Wih^T + enc_bih ----------------
__global__ __launch_bounds__(384) void gi_kernel(const float* __restrict__ x,
                                                 const float* __restrict__ wih,
                                                 const float* __restrict__ bih)
{
    __shared__ float xs[32 * XDIM];
    int tid = threadIdx.x;
    int r0  = blockIdx.x * 32;
    for (int i = tid; i < 32 * XDIM; i += 384) xs[i] = x[(size_t)r0 * XDIM + i];
    __syncthreads();

    float w[XDIM];
#pragma unroll
    for (int p = 0; p < XDIM; ++p) w[p] = wih[tid * XDIM + p];
    float bias = bih[tid];

    for (int b = 0; b < 32; ++b) {
        float acc = bias;
#pragma unroll
        for (int p = 0; p < XDIM; ++p) acc = fmaf(xs[b * XDIM + p], w[p], acc);
        int row = r0 + b;
        g_gi[((size_t)(row & 127) * NBATCH + (row >> 7)) * GDIM + tid] = acc;
    }
}

// stage fp16 W (row-major src) into smem (stride 272B)
__device__ __forceinline__ void stage_w(char* smem, const float* src, int row, int k) {
    *(__half*)(smem + row * WSTR + k * 2) = __float2half_rn(src[k]);
}
// write h hi/lo fp16 tiles at (c, j)
__device__ __forceinline__ void put_h(char* smem, uint32_t obhi, uint32_t oblo,
                                      int c, int j, float hv) {
    __half hb = __float2half_rn(hv);
    *(__half*)(smem + obhi + c * WSTR + j * 2) = hb;
    *(__half*)(smem + oblo + c * WSTR + j * 2) = __float2half_rn(hv - __half2float(hb));
}

// ---------------- encoder recurrence (fp16 2-pass mma) ----------------
__global__ __launch_bounds__(512, 1) void enc_tc_kernel(const float* __restrict__ eWhh,
                                                        const float* __restrict__ bhh)
{
    extern __shared__ char smem[];
    uint32_t sb = smem_u32(smem);
    int tid = threadIdx.x, wid = tid >> 5, lane = tid & 31;
    int b0 = blockIdx.x * TB;
    float* Gf = (float*)(smem + E_G);

    // stage fp16 W
    for (int i = tid; i < GDIM * HDIM; i += 512)
        stage_w(smem + E_W, eWhh + (i >> 7) * HDIM, i >> 7, i & 127);
    // zero h tiles
    for (int i = tid; i < TB * HDIM; i += 512) {
        int c = i >> 7, j = i & 127;
        *(__half*)(smem + E_BHI + c * WSTR + j * 2) = __float2half_rn(0.f);
        *(__half*)(smem + E_BLO + c * WSTR + j * 2) = __float2half_rn(0.f);
    }
    __syncthreads();

    // resident W fragments (warps 0-11: 32 gate rows each)
    uint32_t whi[2][8][4];
    uint32_t baseA = sb + E_W + (wid * 32 + (lane & 15)) * WSTR + (lane >> 4) * 16;
    if (wid < 12) {
#pragma unroll
        for (int m = 0; m < 2; ++m)
#pragma unroll
            for (int kc = 0; kc < 8; ++kc)
                LDSM4(whi[m][kc], baseA + m * 16 * WSTR + kc * 32);
    }

    int jj = tid & 127, c0 = tid >> 7;
    float bh_r = bhh[jj], bh_z = bhh[jj + 128], bh_n = bhh[jj + 256];
    uint32_t baseBh = sb + E_BHI + (lane & 7) * WSTR + (lane >> 3) * 16;
    uint32_t baseBl = sb + E_BLO + (lane & 7) * WSTR + (lane >> 3) * 16;
    int gq = lane >> 2, tig = lane & 3;
    float hreg[4] = {0.f, 0.f, 0.f, 0.f};
    __syncthreads();

    for (int t = 0; t < T_SEQ; ++t) {
        // prefetch gi (overlaps mma)
        float gir[4], giz[4], gin[4];
        const float* gp = g_gi + ((size_t)t * NBATCH + b0) * GDIM;
#pragma unroll
        for (int i = 0; i < 4; ++i) {
            int c = c0 + i * 4;
            gir[i] = gp[c * GDIM + jj];
            giz[i] = gp[c * GDIM + 128 + jj];
            gin[i] = gp[c * GDIM + 256 + jj];
        }

        if (wid < 12) {
            float d[2][2][4];
#pragma unroll
            for (int m = 0; m < 2; ++m)
#pragma unroll
                for (int n = 0; n < 2; ++n)
#pragma unroll
                    for (int q = 0; q < 4; ++q) d[m][n][q] = 0.f;

#pragma unroll
            for (int kp = 0; kp < 4; ++kp) {
                uint32_t bhv[2][4], blv[2][4];
                LDSM4(bhv[0], baseBh + kp * 64);
                LDSM4(bhv[1], baseBh + 8 * WSTR + kp * 64);
                LDSM4(blv[0], baseBl + kp * 64);
                LDSM4(blv[1], baseBl + 8 * WSTR + kp * 64);
#pragma unroll
                for (int ch = 0; ch < 2; ++ch) {
                    int kc = kp * 2 + ch;
#pragma unroll
                    for (int m = 0; m < 2; ++m)
#pragma unroll
                        for (int n = 0; n < 2; ++n) {
                            MMA16816(d[m][n], whi[m][kc], bhv[n][2 * ch], bhv[n][2 * ch + 1]);
                            MMA16816(d[m][n], whi[m][kc], blv[n][2 * ch], blv[n][2 * ch + 1]);
                        }
                }
            }
#pragma unroll
            for (int m = 0; m < 2; ++m)
#pragma unroll
                for (int n = 0; n < 2; ++n) {
                    int row = wid * 32 + m * 16 + gq;
                    int col = n * 8 + 2 * tig;
                    Gf[row * GSTR + col]           = d[m][n][0];
                    Gf[row * GSTR + col + 1]       = d[m][n][1];
                    Gf[(row + 8) * GSTR + col]     = d[m][n][2];
                    Gf[(row + 8) * GSTR + col + 1] = d[m][n][3];
                }
        }
        __syncthreads();

#pragma unroll
        for (int i = 0; i < 4; ++i) {
            int c = c0 + i * 4;
            float r = sigf(gir[i] + bh_r + Gf[jj * GSTR + c]);
            float z = sigf(giz[i] + bh_z + Gf[(128 + jj) * GSTR + c]);
            float n = tanhf_(gin[i] + r * (Gf[(256 + jj) * GSTR + c] + bh_n));
            float h = hreg[i];
            float hv = n + z * (h - n);
            hreg[i] = hv;
            put_h(smem, E_BHI, E_BLO, c, jj, hv);
        }
        __syncthreads();
    }

#pragma unroll
    for (int i = 0; i < 4; ++i) {
        int c = c0 + i * 4;
        g_h0[(size_t)(b0 + c) * HDIM + jj] = hreg[i];
    }
}

// ---------------- decoder t=0 (plain FFMA) ----------------
__global__ __launch_bounds__(512, 1) void dec0_kernel(const float* __restrict__ dbih,
                                                      const float* __restrict__ dbhh)
{
    __shared__ float4 hs4[TB * 32];
    float* hs = (float*)hs4;
    int tid = threadIdx.x;
    int j = tid & 127, s = tid >> 7;
    int b0 = blockIdx.x * TB;

    for (int i = tid; i < TB * HDIM; i += 512) hs[i] = g_h0[(size_t)b0 * HDIM + i];
    float bi_r = dbih[j], bi_z = dbih[j + 128], bi_n = dbih[j + 256];
    __syncthreads();

    float ar[4] = {0, 0, 0, 0}, az[4] = {0, 0, 0, 0}, an[4] = {0, 0, 0, 0};
#pragma unroll 4
    for (int kc = 0; kc < 32; ++kc) {
        float4 wr = g_dWhh4[kc * GDIM + j];
        float4 wz = g_dWhh4[kc * GDIM + 128 + j];
        float4 wn = g_dWhh4[kc * GDIM + 256 + j];
#pragma unroll
        for (int nn = 0; nn < 4; ++nn) {
            float4 hv = hs4[(s + nn * 4) * 32 + kc];
            ar[nn] = fmaf(hv.x, wr.x, ar[nn]); ar[nn] = fmaf(hv.y, wr.y, ar[nn]);
            ar[nn] = fmaf(hv.z, wr.z, ar[nn]); ar[nn] = fmaf(hv.w, wr.w, ar[nn]);
            az[nn] = fmaf(hv.x, wz.x, az[nn]); az[nn] = fmaf(hv.y, wz.y, az[nn]);
            az[nn] = fmaf(hv.z, wz.z, az[nn]); az[nn] = fmaf(hv.w, wz.w, az[nn]);
            an[nn] = fmaf(hv.x, wn.x, an[nn]); an[nn] = fmaf(hv.y, wn.y, an[nn]);
            an[nn] = fmaf(hv.z, wn.z, an[nn]); an[nn] = fmaf(hv.w, wn.w, an[nn]);
        }
    }
    float bh_r = dbhh[j], bh_z = dbhh[j + 128], bh_n = dbhh[j + 256];
#pragma unroll
    for (int nn = 0; nn < 4; ++nn) {
        int b = s + nn * 4;
        float r = sigf(bi_r + bh_r + ar[nn]);
        float z = sigf(bi_z + bh_z + az[nn]);
        float n = tanhf_(bi_n + r * (an[nn] + bh_n));
        float h = hs[b * HDIM + j];
        float hv = n + z * (h - n);
        g_hall[((size_t)(b0 + b) * T_SEQ + 0) * HDIM + j] = hv;
        g_h1[(size_t)(b0 + b) * HDIM + j] = hv;
    }
}

// ---------------- decoder recurrence t=1..127 (fp16 2-pass mma) ----------------
__global__ __launch_bounds__(512, 1) void dec_tc_kernel(const float* __restrict__ dWhh,
                                                        const float* __restrict__ dbhh)
{
    extern __shared__ char smem[];
    uint32_t sb = smem_u32(smem);
    int tid = threadIdx.x, wid = tid >> 5, lane = tid & 31;
    int b0 = blockIdx.x * TB;
    float* Gf = (float*)(smem + D_G);

    // stage fp16 W (rows 0-255 Wrz, 256-383 dWhh n, 384-511 Wcn)
    for (int i = tid; i < 512 * HDIM; i += 512) {
        int row = i >> 7, k = i & 127;
        const float* src = (row < 256) ? (g_Wrz_rm + (size_t)row * HDIM)
                        : (row < 384) ? (dWhh + (size_t)row * HDIM)
                                      : (g_Wcn_rm + (size_t)(row - 384) * HDIM);
        stage_w(smem + D_W, src, row, k);
    }
    __syncthreads();

    uint32_t whi[2][8][4];
    uint32_t baseA = sb + D_W + (wid * 32 + (lane & 15)) * WSTR + (lane >> 4) * 16;
#pragma unroll
    for (int m = 0; m < 2; ++m)
#pragma unroll
        for (int kc = 0; kc < 8; ++kc)
            LDSM4(whi[m][kc], baseA + m * 16 * WSTR + kc * 32);

    int jj = tid & 127, c0 = tid >> 7;
    float hreg[4];
#pragma unroll
    for (int i = 0; i < 4; ++i) {
        int c = c0 + i * 4;
        float hv = g_h1[(size_t)(b0 + c) * HDIM + jj];
        hreg[i] = hv;
        put_h(smem, D_BHI, D_BLO, c, jj, hv);
    }

    float brz_r = g_brz[jj], brz_z = g_brz[jj + 128];
    float bcn = g_bcomb[jj + 256], bh_n = dbhh[jj + 256];
    uint32_t baseBh = sb + D_BHI + (lane & 7) * WSTR + (lane >> 3) * 16;
    uint32_t baseBl = sb + D_BLO + (lane & 7) * WSTR + (lane >> 3) * 16;
    int gq = lane >> 2, tig = lane & 3;
    __syncthreads();

    for (int tt = 0; tt < T_SEQ - 1; ++tt) {
        float d[2][2][4];
#pragma unroll
        for (int m = 0; m < 2; ++m)
#pragma unroll
            for (int n = 0; n < 2; ++n)
#pragma unroll
                for (int q = 0; q < 4; ++q) d[m][n][q] = 0.f;

#pragma unroll
        for (int kp = 0; kp < 4; ++kp) {
            uint32_t bhv[2][4], blv[2][4];
            LDSM4(bhv[0], baseBh + kp * 64);
            LDSM4(bhv[1], baseBh + 8 * WSTR + kp * 64);
            LDSM4(blv[0], baseBl + kp * 64);
            LDSM4(blv[1], baseBl + 8 * WSTR + kp * 64);
#pragma unroll
            for (int ch = 0; ch < 2; ++ch) {
                int kc = kp * 2 + ch;
#pragma unroll
                for (int m = 0; m < 2; ++m)
#pragma unroll
                    for (int n = 0; n < 2; ++n) {
                        MMA16816(d[m][n], whi[m][kc], bhv[n][2 * ch], bhv[n][2 * ch + 1]);
                        MMA16816(d[m][n], whi[m][kc], blv[n][2 * ch], blv[n][2 * ch + 1]);
                    }
            }
        }
#pragma unroll
        for (int m = 0; m < 2; ++m)
#pragma unroll
            for (int n = 0; n < 2; ++n) {
                int row = wid * 32 + m * 16 + gq;
                int col = n * 8 + 2 * tig;
                Gf[row * GSTR + col]           = d[m][n][0];
                Gf[row * GSTR + col + 1]       = d[m][n][1];
                Gf[(row + 8) * GSTR + col]     = d[m][n][2];
                Gf[(row + 8) * GSTR + col + 1] = d[m][n][3];
            }
        __syncthreads();

#pragma unroll
        for (int i = 0; i < 4; ++i) {
            int c = c0 + i * 4;
            float r = sigf(brz_r + Gf[jj * GSTR + c]);
            float z = sigf(brz_z + Gf[(128 + jj) * GSTR + c]);
            float n = tanhf_(bcn + Gf[(384 + jj) * GSTR + c]
                             + r * (Gf[(256 + jj) * GSTR + c] + bh_n));
            float h = hreg[i];
            float hv = n + z * (h - n);
            hreg[i] = hv;
            g_hall[((size_t)(b0 + c) * T_SEQ + tt + 1) * HDIM + jj] = hv;
            put_h(smem, D_BHI, D_BLO, c, jj, hv);
        }
        __syncthreads();
    }
}

// ---------------- out = g_hall @ lin_W^T + lin_b ----------------
__global__ void out_kernel(const float* __restrict__ linW, const float* __restrict__ linb,
                           float* __restrict__ out)
{
    __shared__ float hS[16 * HDIM];
    __shared__ float lS[HDIM * XDIM];
    int tx = threadIdx.x, ty = threadIdx.y;
    int tid = ty * XDIM + tx;
    int nthr = XDIM * 16;
    size_t r0 = (size_t)blockIdx.x * 16;

    for (int i = tid; i < 16 * HDIM; i += nthr) hS[i] = g_hall[r0 * HDIM + i];
    for (int i = tid; i < HDIM * XDIM; i += nthr) {
        int k = i / XDIM, p = i - k * XDIM;
        lS[i] = linW[p * HDIM + k];
    }
    __syncthreads();

    float acc = linb[tx];
    const float* hrow = hS + ty * HDIM;
#pragma unroll 8
    for (int k = 0; k < HDIM; ++k) acc = fmaf(hrow[k], lS[k * XDIM + tx], acc);
    out[(r0 + ty) * XDIM + tx] = acc;
}

// ---------------- launch ----------------
extern "C" void kernel_launch(void* const* d_in, const int* in_sizes, int n_in,
                              void* d_out, int out_size) {
    const float* x        = (const float*)d_in[0];
    const float* enc_Wih  = (const float*)d_in[1];
    const float* enc_Whh  = (const float*)d_in[2];
    const float* enc_bih  = (const float*)d_in[3];
    const float* enc_bhh  = (const float*)d_in[4];
    const float* dec_Wih  = (const float*)d_in[5];
    const float* dec_Whh  = (const float*)d_in[6];
    const float* dec_bih  = (const float*)d_in[7];
    const float* dec_bhh  = (const float*)d_in[8];
    const float* lin_W    = (const float*)d_in[9];
    const float* lin_b    = (const float*)d_in[10];
    float* out = (float*)d_out;

    cudaFuncSetAttribute(enc_tc_kernel, cudaFuncAttributeMaxDynamicSharedMemorySize, E_SZ);
    cudaFuncSetAttribute(dec_tc_kernel, cudaFuncAttributeMaxDynamicSharedMemorySize, D_SZ);

    prep_kernel<<<3, 128>>>(dec_Whh, dec_Wih, lin_W, lin_b, dec_bih, dec_bhh);
    gi_kernel<<<(T_SEQ * NBATCH) / 32, 384>>>(x, enc_Wih, enc_bih);
    enc_tc_kernel<<<NBATCH / TB, 512, E_SZ>>>(enc_Whh, enc_bhh);
    dec0_kernel<<<NBATCH / TB, 512>>>(dec_bih, dec_bhh);
    dec_tc_kernel<<<NBATCH / TB, 512, D_SZ>>>(dec_Whh, dec_bhh);
    out_kernel<<<(NBATCH * T_SEQ) / 16, dim3(XDIM, 16)>>>(lin_W, lin_b, out);
}